// round 11
// baseline (speedup 1.0000x reference)
#include <cuda_runtime.h>
#include <cuda_bf16.h>
#include <stdint.h>

#define BATCH 16
#define HH    128
#define WW    128
#define HID   16
#define KS    9
#define NBLK  50
#define CH_PAD 64
#define HP    136            // 128 + 4 halo each side
#define G     8              // output rows per CTA (2 warps per row)
#define MAXCK 4
#define NT    512            // threads per CTA (16 warps)

#define A_HL_BYTES (16 * HP * 32)        // 16 rows x 136 slots x 32B = 69632
#define SM_A_BYTES (2 * A_HL_BYTES)      // hi + lo = 139264
#define SM_B_BYTES (81 * 1024)           // 81 taps x [hl2][c16][oc16] bf16 = 82944
#define SM_TOTAL   (SM_A_BYTES + SM_B_BYTES)   // 222208

// features, channel-interleaved: idx ((b*HP+h)*HP+x)*CH_PAD + c ; halo stays 0
__device__ __align__(16) __nv_bfloat16 g_hi[(size_t)BATCH * HP * HP * CH_PAD];
__device__ __align__(16) __nv_bfloat16 g_lo[(size_t)BATCH * HP * HP * CH_PAD];
// weights per (blk,ck): [tap81][hl2][c16][oc16] bf16, 512 elems/tap
__device__ __align__(16) __nv_bfloat16 g_wb[(size_t)NBLK * MAXCK * 81 * 512];

__device__ __forceinline__ uint32_t sptr(const void* p) {
    return (uint32_t)__cvta_generic_to_shared(p);
}
__device__ __forceinline__ void ldsm4(uint32_t* r, uint32_t a) {
    asm volatile("ldmatrix.sync.aligned.m8n8.x4.shared.b16 {%0,%1,%2,%3}, [%4];"
        : "=r"(r[0]), "=r"(r[1]), "=r"(r[2]), "=r"(r[3]) : "r"(a));
}
__device__ __forceinline__ void ldsm4t(uint32_t* r, uint32_t a) {
    asm volatile("ldmatrix.sync.aligned.m8n8.x4.trans.shared.b16 {%0,%1,%2,%3}, [%4];"
        : "=r"(r[0]), "=r"(r[1]), "=r"(r[2]), "=r"(r[3]) : "r"(a));
}
__device__ __forceinline__ void mma16816(float* c, const uint32_t* a,
                                         uint32_t b0, uint32_t b1) {
    asm volatile(
        "mma.sync.aligned.m16n8k16.row.col.f32.bf16.bf16.f32 "
        "{%0,%1,%2,%3},{%4,%5,%6,%7},{%8,%9},{%0,%1,%2,%3};"
        : "+f"(c[0]), "+f"(c[1]), "+f"(c[2]), "+f"(c[3])
        : "r"(a[0]), "r"(a[1]), "r"(a[2]), "r"(a[3]), "r"(b0), "r"(b1));
}

// ---- prep: split weights into bf16 hi/lo, layout [tap][hl][c16][oc16] ----
__global__ void prep_w_kernel(const float* __restrict__ w1) {
    int bi  = blockIdx.x;                 // NBLK*MAXCK*81
    int tap = bi % 81;
    int ck  = (bi / 81) & 3;
    int blk = bi / (81 * 4);
    int oc  = threadIdx.x & 15;
    int c   = threadIdx.x >> 4;
    int cg  = ck * 16 + c;
    float w = 0.f;
    if (cg < blk + 1)
        w = w1[(((size_t)blk * HID + oc) * (NBLK + 1) + cg) * 81 + tap];
    __nv_bfloat16 hi = __float2bfloat16(w);
    __nv_bfloat16 lo = __float2bfloat16(w - __bfloat162float(hi));
    size_t base = ((size_t)(blk * MAXCK + ck) * 81 + tap) * 512;
    g_wb[base +       c * 16 + oc] = hi;
    g_wb[base + 256 + c * 16 + oc] = lo;
}

__global__ void copy_x_kernel(const float* __restrict__ x) {
    int t = blockIdx.x * blockDim.x + threadIdx.x;   // b*H*W
    int w = t & (WW - 1), h = (t >> 7) & (HH - 1), b = t >> 14;
    float v = x[t];
    __nv_bfloat16 hi = __float2bfloat16(v);
    __nv_bfloat16 lo = __float2bfloat16(v - __bfloat162float(hi));
    size_t gi = (((size_t)b * HP + h + 4) * HP + w + 4) * CH_PAD;
    g_hi[gi] = hi; g_lo[gi] = lo;
}

__global__ void __launch_bounds__(NT, 1) dense_block_mma(
    const float* __restrict__ b1, const float* __restrict__ w2,
    const float* __restrict__ b2, float* __restrict__ out, int blk)
{
    extern __shared__ __align__(128) char smem[];
    const int tid  = threadIdx.x;
    const int wid  = tid >> 5;           // 0..15
    const int lane = tid & 31;
    const int row  = wid >> 1;           // output row within CTA (0..7)
    const int half = wid & 1;            // pixel half: 0 -> px 0-63, 1 -> 64-127
    const int gid  = lane >> 2;          // 0..7
    const int tig  = lane & 3;           // 0..3
    const int r0   = blockIdx.x * G;     // output row base
    const int bb   = blockIdx.y;

    const uint32_t sA = sptr(smem);
    const uint32_t sB = sA + SM_A_BYTES;
    const uint32_t laneoff = (uint32_t)((lane & 15) * 32 + (lane >> 4) * 16);

    float acc[4][2][4];   // 4 m-tiles x 2 oc-halves x 4
    #pragma unroll
    for (int t = 0; t < 4; ++t)
        #pragma unroll
        for (int nh = 0; nh < 2; ++nh)
            #pragma unroll
            for (int q = 0; q < 4; ++q) acc[t][nh][q] = 0.f;

    const int nchunks = (blk + 16) >> 4;

    for (int ck = 0; ck < nchunks; ++ck) {
        __syncthreads();   // previous chunk's readers done

        // B: straight 82944B copy
        {
            const float4* src = (const float4*)(g_wb + ((size_t)blk * MAXCK + ck) * 81 * 512);
            float4* dst = (float4*)(smem + SM_A_BYTES);
            for (int i = tid; i < SM_B_BYTES / 16; i += NT) dst[i] = src[i];
        }
        // A: 16 rows x 136 slots, hi plane then lo plane
        {
            const int c0 = ck * 16;
            float4* pa = (float4*)smem;
            for (int s = tid; s < 16 * HP; s += NT) {
                int lr = s / HP, xs = s - lr * HP;
                size_t gi = (((size_t)bb * HP + r0 + lr) * HP + xs) * CH_PAD + c0;
                int d = s * 2;
                pa[d]            = *(const float4*)(g_hi + gi);
                pa[d + 1]        = *(const float4*)(g_hi + gi + 8);
                pa[4352 + d]     = *(const float4*)(g_lo + gi);
                pa[4352 + d + 1] = *(const float4*)(g_lo + gi + 8);
            }
        }
        __syncthreads();

        #pragma unroll 1
        for (int kh = 0; kh < KS; ++kh) {
            const uint32_t aRowHi = sA + (row + kh) * 4352 + laneoff
                                  + (uint32_t)(64 * half) * 32;
            const uint32_t aRowLo = aRowHi + A_HL_BYTES;
            const uint32_t bRow   = sB + kh * KS * 1024 + laneoff;
            #pragma unroll
            for (int kw = 0; kw < KS; ++kw) {
                // ---- batched load phase: 10 LDSM back-to-back (MLP=10) ----
                uint32_t bh[4], bl[4], ahi[4][4], alo[4][4];
                ldsm4t(bh, bRow + kw * 1024);
                ldsm4t(bl, bRow + kw * 1024 + 512);
                #pragma unroll
                for (int t = 0; t < 4; ++t) {
                    const uint32_t aoff = (uint32_t)((16 * t + kw) * 32);
                    ldsm4(ahi[t], aRowHi + aoff);
                    ldsm4(alo[t], aRowLo + aoff);
                }
                // ---- MMA phase: same-acc chains spaced 8 apart ----
                #pragma unroll
                for (int t = 0; t < 4; ++t) mma16816(acc[t][0], ahi[t], bh[0], bh[1]);
                #pragma unroll
                for (int t = 0; t < 4; ++t) mma16816(acc[t][1], ahi[t], bh[2], bh[3]);
                #pragma unroll
                for (int t = 0; t < 4; ++t) mma16816(acc[t][0], ahi[t], bl[0], bl[1]);
                #pragma unroll
                for (int t = 0; t < 4; ++t) mma16816(acc[t][1], ahi[t], bl[2], bl[3]);
                #pragma unroll
                for (int t = 0; t < 4; ++t) mma16816(acc[t][0], alo[t], bh[0], bh[1]);
                #pragma unroll
                for (int t = 0; t < 4; ++t) mma16816(acc[t][1], alo[t], bh[2], bh[3]);
            }
        }
    }

    // ---- epilogue ----
    // thread's 4 output channels: o0=2*tig, o0+1, o0+8, o0+9
    const int o0 = 2 * tig;
    const float b1a = __ldg(&b1[blk * HID + o0]);
    const float b1b = __ldg(&b1[blk * HID + o0 + 1]);
    const float b1c = __ldg(&b1[blk * HID + o0 + 8]);
    const float b1d = __ldg(&b1[blk * HID + o0 + 9]);
    const float w2a = __ldg(&w2[blk * HID + o0]);
    const float w2b = __ldg(&w2[blk * HID + o0 + 1]);
    const float w2c = __ldg(&w2[blk * HID + o0 + 8]);
    const float w2d = __ldg(&w2[blk * HID + o0 + 9]);
    const float b2v = __ldg(&b2[blk]);
    const int h = r0 + row;

    #pragma unroll
    for (int t = 0; t < 4; ++t) {
        #pragma unroll
        for (int mh = 0; mh < 2; ++mh) {  // mh 0: pixel gid (c0,c1), 1: gid+8 (c2,c3)
            float s = fmaxf(acc[t][0][2 * mh]     + b1a, 0.f) * w2a
                    + fmaxf(acc[t][0][2 * mh + 1] + b1b, 0.f) * w2b
                    + fmaxf(acc[t][1][2 * mh]     + b1c, 0.f) * w2c
                    + fmaxf(acc[t][1][2 * mh + 1] + b1d, 0.f) * w2d;
            s += __shfl_xor_sync(0xffffffffu, s, 1);
            s += __shfl_xor_sync(0xffffffffu, s, 2);
            if (tig == 0) {
                const int px = 64 * half + 16 * t + gid + 8 * mh;
                const float y = 1.0f / (1.0f + __expf(-(s + b2v)));
                out[(((size_t)bb * NBLK + blk) * HH + h) * WW + px] = y;
                __nv_bfloat16 hi = __float2bfloat16(y);
                __nv_bfloat16 lo = __float2bfloat16(y - __bfloat162float(hi));
                size_t gi = (((size_t)bb * HP + h + 4) * HP + px + 4) * CH_PAD + blk + 1;
                g_hi[gi] = hi; g_lo[gi] = lo;
            }
        }
    }
}

extern "C" void kernel_launch(void* const* d_in, const int* in_sizes, int n_in,
                              void* d_out, int out_size) {
    const float* x  = (const float*)d_in[0];
    const float* w1 = (const float*)d_in[1];
    const float* b1 = (const float*)d_in[2];
    const float* w2 = (const float*)d_in[3];
    const float* b2 = (const float*)d_in[4];
    float* out = (float*)d_out;

    cudaFuncSetAttribute(dense_block_mma,
                         cudaFuncAttributeMaxDynamicSharedMemorySize, SM_TOTAL);

    prep_w_kernel<<<NBLK * MAXCK * 81, 256>>>(w1);          // 16200 blocks
    copy_x_kernel<<<(BATCH * HH * WW) / 256, 256>>>(x);

    dim3 grid(HH / G, BATCH);                               // 16 x 16 = 256 CTAs
    for (int i = 0; i < NBLK; ++i)
        dense_block_mma<<<grid, NT, SM_TOTAL>>>(b1, w2, b2, out, i);
}

// round 12
// speedup vs baseline: 1.3078x; 1.3078x over previous
#include <cuda_runtime.h>
#include <cuda_bf16.h>
#include <stdint.h>

#define BATCH 16
#define HH    128
#define WW    128
#define HID   16
#define KS    9
#define NBLK  50
#define CH_PAD 64
#define HP    136            // 128 + 4 halo each side
#define G     8              // output rows per CTA (4 warps per row)
#define MAXCK 4
#define NT    1024           // threads per CTA (32 warps)

#define A_HL_BYTES (16 * HP * 32)        // 16 rows x 136 slots x 32B = 69632
#define SM_A_BYTES (2 * A_HL_BYTES)      // hi + lo = 139264
#define SM_B_BYTES (81 * 1024)           // 81 taps x [hl2][c16][oc16] bf16 = 82944
#define SM_TOTAL   (SM_A_BYTES + SM_B_BYTES)   // 222208

// features, channel-interleaved: idx ((b*HP+h)*HP+x)*CH_PAD + c ; halo stays 0
__device__ __align__(16) __nv_bfloat16 g_hi[(size_t)BATCH * HP * HP * CH_PAD];
__device__ __align__(16) __nv_bfloat16 g_lo[(size_t)BATCH * HP * HP * CH_PAD];
// weights per (blk,ck): [tap81][hl2][c16][oc16] bf16, 512 elems/tap
__device__ __align__(16) __nv_bfloat16 g_wb[(size_t)NBLK * MAXCK * 81 * 512];

__device__ __forceinline__ uint32_t sptr(const void* p) {
    return (uint32_t)__cvta_generic_to_shared(p);
}
__device__ __forceinline__ void ldsm4(uint32_t* r, uint32_t a) {
    asm volatile("ldmatrix.sync.aligned.m8n8.x4.shared.b16 {%0,%1,%2,%3}, [%4];"
        : "=r"(r[0]), "=r"(r[1]), "=r"(r[2]), "=r"(r[3]) : "r"(a));
}
__device__ __forceinline__ void ldsm4t(uint32_t* r, uint32_t a) {
    asm volatile("ldmatrix.sync.aligned.m8n8.x4.trans.shared.b16 {%0,%1,%2,%3}, [%4];"
        : "=r"(r[0]), "=r"(r[1]), "=r"(r[2]), "=r"(r[3]) : "r"(a));
}
__device__ __forceinline__ void mma16816(float* c, const uint32_t* a,
                                         uint32_t b0, uint32_t b1) {
    asm volatile(
        "mma.sync.aligned.m16n8k16.row.col.f32.bf16.bf16.f32 "
        "{%0,%1,%2,%3},{%4,%5,%6,%7},{%8,%9},{%0,%1,%2,%3};"
        : "+f"(c[0]), "+f"(c[1]), "+f"(c[2]), "+f"(c[3])
        : "r"(a[0]), "r"(a[1]), "r"(a[2]), "r"(a[3]), "r"(b0), "r"(b1));
}

// ---- prep: split weights into bf16 hi/lo, layout [tap][hl][c16][oc16] ----
__global__ void prep_w_kernel(const float* __restrict__ w1) {
    int bi  = blockIdx.x;                 // NBLK*MAXCK*81
    int tap = bi % 81;
    int ck  = (bi / 81) & 3;
    int blk = bi / (81 * 4);
    int oc  = threadIdx.x & 15;
    int c   = threadIdx.x >> 4;
    int cg  = ck * 16 + c;
    float w = 0.f;
    if (cg < blk + 1)
        w = w1[(((size_t)blk * HID + oc) * (NBLK + 1) + cg) * 81 + tap];
    __nv_bfloat16 hi = __float2bfloat16(w);
    __nv_bfloat16 lo = __float2bfloat16(w - __bfloat162float(hi));
    size_t base = ((size_t)(blk * MAXCK + ck) * 81 + tap) * 512;
    g_wb[base +       c * 16 + oc] = hi;
    g_wb[base + 256 + c * 16 + oc] = lo;
}

__global__ void copy_x_kernel(const float* __restrict__ x) {
    int t = blockIdx.x * blockDim.x + threadIdx.x;   // b*H*W
    int w = t & (WW - 1), h = (t >> 7) & (HH - 1), b = t >> 14;
    float v = x[t];
    __nv_bfloat16 hi = __float2bfloat16(v);
    __nv_bfloat16 lo = __float2bfloat16(v - __bfloat162float(hi));
    size_t gi = (((size_t)b * HP + h + 4) * HP + w + 4) * CH_PAD;
    g_hi[gi] = hi; g_lo[gi] = lo;
}

__global__ void __launch_bounds__(NT, 1) dense_block_mma(
    const float* __restrict__ b1, const float* __restrict__ w2,
    const float* __restrict__ b2, float* __restrict__ out, int blk)
{
    extern __shared__ __align__(128) char smem[];
    const int tid  = threadIdx.x;
    const int wid  = tid >> 5;           // 0..31
    const int lane = tid & 31;
    const int row  = wid >> 2;           // output row within CTA (0..7)
    const int qtr  = wid & 3;            // pixel quarter: 32 px each
    const int gid  = lane >> 2;          // 0..7
    const int tig  = lane & 3;           // 0..3
    const int r0   = blockIdx.x * G;     // output row base
    const int bb   = blockIdx.y;

    const uint32_t sA = sptr(smem);
    const uint32_t sB = sA + SM_A_BYTES;
    const uint32_t laneoff = (uint32_t)((lane & 15) * 32 + (lane >> 4) * 16);

    float acc[2][2][4];   // 2 m-tiles x 2 oc-halves x 4
    #pragma unroll
    for (int t = 0; t < 2; ++t)
        #pragma unroll
        for (int nh = 0; nh < 2; ++nh)
            #pragma unroll
            for (int q = 0; q < 4; ++q) acc[t][nh][q] = 0.f;

    const int nchunks = (blk + 16) >> 4;

    for (int ck = 0; ck < nchunks; ++ck) {
        __syncthreads();   // previous chunk's readers done

        // B: straight 82944B copy
        {
            const float4* src = (const float4*)(g_wb + ((size_t)blk * MAXCK + ck) * 81 * 512);
            float4* dst = (float4*)(smem + SM_A_BYTES);
            for (int i = tid; i < SM_B_BYTES / 16; i += NT) dst[i] = src[i];
        }
        // A: 16 rows x 136 slots, hi plane then lo plane
        {
            const int c0 = ck * 16;
            float4* pa = (float4*)smem;
            for (int s = tid; s < 16 * HP; s += NT) {
                int lr = s / HP, xs = s - lr * HP;
                size_t gi = (((size_t)bb * HP + r0 + lr) * HP + xs) * CH_PAD + c0;
                int d = s * 2;
                pa[d]            = *(const float4*)(g_hi + gi);
                pa[d + 1]        = *(const float4*)(g_hi + gi + 8);
                pa[4352 + d]     = *(const float4*)(g_lo + gi);
                pa[4352 + d + 1] = *(const float4*)(g_lo + gi + 8);
            }
        }
        __syncthreads();

        #pragma unroll 1
        for (int kh = 0; kh < KS; ++kh) {
            const uint32_t aRowHi = sA + (row + kh) * 4352 + laneoff
                                  + (uint32_t)(32 * qtr) * 32;
            const uint32_t aRowLo = aRowHi + A_HL_BYTES;
            #pragma unroll 1
            for (int kw = 0; kw < KS; ++kw) {
                const uint32_t bTap = sB + (kh * KS + kw) * 1024 + laneoff;
                uint32_t bh[4], bl[4];
                ldsm4t(bh, bTap);        // [c16][oc16] hi
                ldsm4t(bl, bTap + 512);  // lo
                #pragma unroll
                for (int t = 0; t < 2; ++t) {
                    const uint32_t aoff = (uint32_t)((16 * t + kw) * 32);
                    uint32_t ahi[4], alo[4];
                    ldsm4(ahi, aRowHi + aoff);
                    mma16816(acc[t][0], ahi, bh[0], bh[1]);
                    mma16816(acc[t][1], ahi, bh[2], bh[3]);
                    mma16816(acc[t][0], ahi, bl[0], bl[1]);
                    mma16816(acc[t][1], ahi, bl[2], bl[3]);
                    ldsm4(alo, aRowLo + aoff);
                    mma16816(acc[t][0], alo, bh[0], bh[1]);
                    mma16816(acc[t][1], alo, bh[2], bh[3]);
                }
            }
        }
    }

    // ---- epilogue ----
    // thread's 4 output channels: o0=2*tig, o0+1, o0+8, o0+9
    const int o0 = 2 * tig;
    const float b1a = __ldg(&b1[blk * HID + o0]);
    const float b1b = __ldg(&b1[blk * HID + o0 + 1]);
    const float b1c = __ldg(&b1[blk * HID + o0 + 8]);
    const float b1d = __ldg(&b1[blk * HID + o0 + 9]);
    const float w2a = __ldg(&w2[blk * HID + o0]);
    const float w2b = __ldg(&w2[blk * HID + o0 + 1]);
    const float w2c = __ldg(&w2[blk * HID + o0 + 8]);
    const float w2d = __ldg(&w2[blk * HID + o0 + 9]);
    const float b2v = __ldg(&b2[blk]);
    const int h = r0 + row;

    #pragma unroll
    for (int t = 0; t < 2; ++t) {
        #pragma unroll
        for (int mh = 0; mh < 2; ++mh) {  // mh 0: pixel gid (c0,c1), 1: gid+8 (c2,c3)
            float s = fmaxf(acc[t][0][2 * mh]     + b1a, 0.f) * w2a
                    + fmaxf(acc[t][0][2 * mh + 1] + b1b, 0.f) * w2b
                    + fmaxf(acc[t][1][2 * mh]     + b1c, 0.f) * w2c
                    + fmaxf(acc[t][1][2 * mh + 1] + b1d, 0.f) * w2d;
            s += __shfl_xor_sync(0xffffffffu, s, 1);
            s += __shfl_xor_sync(0xffffffffu, s, 2);
            if (tig == 0) {
                const int px = 32 * qtr + 16 * t + gid + 8 * mh;
                const float y = 1.0f / (1.0f + __expf(-(s + b2v)));
                out[(((size_t)bb * NBLK + blk) * HH + h) * WW + px] = y;
                __nv_bfloat16 hi = __float2bfloat16(y);
                __nv_bfloat16 lo = __float2bfloat16(y - __bfloat162float(hi));
                size_t gi = (((size_t)bb * HP + h + 4) * HP + px + 4) * CH_PAD + blk + 1;
                g_hi[gi] = hi; g_lo[gi] = lo;
            }
        }
    }
}

extern "C" void kernel_launch(void* const* d_in, const int* in_sizes, int n_in,
                              void* d_out, int out_size) {
    const float* x  = (const float*)d_in[0];
    const float* w1 = (const float*)d_in[1];
    const float* b1 = (const float*)d_in[2];
    const float* w2 = (const float*)d_in[3];
    const float* b2 = (const float*)d_in[4];
    float* out = (float*)d_out;

    cudaFuncSetAttribute(dense_block_mma,
                         cudaFuncAttributeMaxDynamicSharedMemorySize, SM_TOTAL);

    prep_w_kernel<<<NBLK * MAXCK * 81, 256>>>(w1);          // 16200 blocks
    copy_x_kernel<<<(BATCH * HH * WW) / 256, 256>>>(x);

    dim3 grid(HH / G, BATCH);                               // 16 x 16 = 256 CTAs
    for (int i = 0; i < NBLK; ++i)
        dense_block_mma<<<grid, NT, SM_TOTAL>>>(b1, w2, b2, out, i);
}

// round 13
// speedup vs baseline: 2.5938x; 1.9834x over previous
#include <cuda_runtime.h>
#include <cuda_fp16.h>
#include <stdint.h>

#define BATCH 16
#define HH    128
#define WW    128
#define HID   16
#define KS    9
#define NBLK  50
#define CH_PAD 64
#define HP    136            // 128 + 4 halo each side
#define G     8              // output rows per CTA (2 warps per row)
#define MAXCK 4
#define NT    512            // threads per CTA (16 warps) — best measured config

#define SM_A_BYTES (16 * HP * 32)        // 16 rows x 136 slots x 32B = 69632 (single plane)
#define SM_B_BYTES (81 * 1024)           // 81 taps x [hl2][c16][oc16] fp16 = 82944
#define SM_TOTAL   (SM_A_BYTES + SM_B_BYTES)   // 152576

// features, single fp16 plane, channel-interleaved: ((b*HP+h)*HP+x)*CH_PAD + c ; halo 0
__device__ __align__(16) __half g_f[(size_t)BATCH * HP * HP * CH_PAD];
// weights per (blk,ck): [tap81][hl2][c16][oc16] fp16 (hi, lo), 512 elems/tap
__device__ __align__(16) __half g_wb[(size_t)NBLK * MAXCK * 81 * 512];

__device__ __forceinline__ uint32_t sptr(const void* p) {
    return (uint32_t)__cvta_generic_to_shared(p);
}
__device__ __forceinline__ void ldsm4(uint32_t* r, uint32_t a) {
    asm volatile("ldmatrix.sync.aligned.m8n8.x4.shared.b16 {%0,%1,%2,%3}, [%4];"
        : "=r"(r[0]), "=r"(r[1]), "=r"(r[2]), "=r"(r[3]) : "r"(a));
}
__device__ __forceinline__ void ldsm4t(uint32_t* r, uint32_t a) {
    asm volatile("ldmatrix.sync.aligned.m8n8.x4.trans.shared.b16 {%0,%1,%2,%3}, [%4];"
        : "=r"(r[0]), "=r"(r[1]), "=r"(r[2]), "=r"(r[3]) : "r"(a));
}
__device__ __forceinline__ void mma16816(float* c, const uint32_t* a,
                                         uint32_t b0, uint32_t b1) {
    asm volatile(
        "mma.sync.aligned.m16n8k16.row.col.f32.f16.f16.f32 "
        "{%0,%1,%2,%3},{%4,%5,%6,%7},{%8,%9},{%0,%1,%2,%3};"
        : "+f"(c[0]), "+f"(c[1]), "+f"(c[2]), "+f"(c[3])
        : "r"(a[0]), "r"(a[1]), "r"(a[2]), "r"(a[3]), "r"(b0), "r"(b1));
}

// ---- prep: split weights into fp16 hi/lo, layout [tap][hl][c16][oc16] ----
__global__ void prep_w_kernel(const float* __restrict__ w1) {
    int bi  = blockIdx.x;                 // NBLK*MAXCK*81
    int tap = bi % 81;
    int ck  = (bi / 81) & 3;
    int blk = bi / (81 * 4);
    int oc  = threadIdx.x & 15;
    int c   = threadIdx.x >> 4;
    int cg  = ck * 16 + c;
    float w = 0.f;
    if (cg < blk + 1)
        w = w1[(((size_t)blk * HID + oc) * (NBLK + 1) + cg) * 81 + tap];
    __half hi = __float2half(w);
    __half lo = __float2half(w - __half2float(hi));
    size_t base = ((size_t)(blk * MAXCK + ck) * 81 + tap) * 512;
    g_wb[base +       c * 16 + oc] = hi;
    g_wb[base + 256 + c * 16 + oc] = lo;
}

__global__ void copy_x_kernel(const float* __restrict__ x) {
    int t = blockIdx.x * blockDim.x + threadIdx.x;   // b*H*W
    int w = t & (WW - 1), h = (t >> 7) & (HH - 1), b = t >> 14;
    size_t gi = (((size_t)b * HP + h + 4) * HP + w + 4) * CH_PAD;
    g_f[gi] = __float2half(x[t]);
}

__global__ void __launch_bounds__(NT, 1) dense_block_mma(
    const float* __restrict__ b1, const float* __restrict__ w2,
    const float* __restrict__ b2, float* __restrict__ out, int blk)
{
    extern __shared__ __align__(128) char smem[];
    const int tid  = threadIdx.x;
    const int wid  = tid >> 5;           // 0..15
    const int lane = tid & 31;
    const int row  = wid >> 1;           // output row within CTA (0..7)
    const int half = wid & 1;            // pixel half: 0 -> px 0-63, 1 -> 64-127
    const int gid  = lane >> 2;          // 0..7
    const int tig  = lane & 3;           // 0..3
    const int r0   = blockIdx.x * G;     // output row base
    const int bb   = blockIdx.y;

    const uint32_t sA = sptr(smem);
    const uint32_t sB = sA + SM_A_BYTES;
    const uint32_t laneoff = (uint32_t)((lane & 15) * 32 + (lane >> 4) * 16);

    float acc[4][2][4];   // 4 m-tiles x 2 oc-halves x 4
    #pragma unroll
    for (int t = 0; t < 4; ++t)
        #pragma unroll
        for (int nh = 0; nh < 2; ++nh)
            #pragma unroll
            for (int q = 0; q < 4; ++q) acc[t][nh][q] = 0.f;

    const int nchunks = (blk + 16) >> 4;

    for (int ck = 0; ck < nchunks; ++ck) {
        __syncthreads();   // previous chunk's readers done

        // B: straight 82944B copy
        {
            const float4* src = (const float4*)(g_wb + ((size_t)blk * MAXCK + ck) * 81 * 512);
            float4* dst = (float4*)(smem + SM_A_BYTES);
            for (int i = tid; i < SM_B_BYTES / 16; i += NT) dst[i] = src[i];
        }
        // A: 16 rows x 136 slots, single fp16 plane (32B per slot)
        {
            const int c0 = ck * 16;
            float4* pa = (float4*)smem;
            for (int s = tid; s < 16 * HP; s += NT) {
                int lr = s / HP, xs = s - lr * HP;
                size_t gi = (((size_t)bb * HP + r0 + lr) * HP + xs) * CH_PAD + c0;
                int d = s * 2;
                pa[d]     = *(const float4*)(g_f + gi);
                pa[d + 1] = *(const float4*)(g_f + gi + 8);
            }
        }
        __syncthreads();

        #pragma unroll 1
        for (int kh = 0; kh < KS; ++kh) {
            const uint32_t aRow = sA + (row + kh) * 4352 + laneoff
                                + (uint32_t)(64 * half) * 32;
            #pragma unroll 1
            for (int kw = 0; kw < KS; ++kw) {
                const uint32_t bTap = sB + (kh * KS + kw) * 1024 + laneoff;
                uint32_t bh[4], bl[4];
                ldsm4t(bh, bTap);        // [c16][oc16] w-hi
                ldsm4t(bl, bTap + 512);  // w-lo
                #pragma unroll
                for (int t = 0; t < 4; ++t) {
                    const uint32_t aoff = (uint32_t)((16 * t + kw) * 32);
                    uint32_t a[4];
                    ldsm4(a, aRow + aoff);
                    mma16816(acc[t][0], a, bh[0], bh[1]);
                    mma16816(acc[t][1], a, bh[2], bh[3]);
                    mma16816(acc[t][0], a, bl[0], bl[1]);
                    mma16816(acc[t][1], a, bl[2], bl[3]);
                }
            }
        }
    }

    // ---- epilogue ----
    // thread's 4 output channels: o0=2*tig, o0+1, o0+8, o0+9
    const int o0 = 2 * tig;
    const float b1a = __ldg(&b1[blk * HID + o0]);
    const float b1b = __ldg(&b1[blk * HID + o0 + 1]);
    const float b1c = __ldg(&b1[blk * HID + o0 + 8]);
    const float b1d = __ldg(&b1[blk * HID + o0 + 9]);
    const float w2a = __ldg(&w2[blk * HID + o0]);
    const float w2b = __ldg(&w2[blk * HID + o0 + 1]);
    const float w2c = __ldg(&w2[blk * HID + o0 + 8]);
    const float w2d = __ldg(&w2[blk * HID + o0 + 9]);
    const float b2v = __ldg(&b2[blk]);
    const int h = r0 + row;

    #pragma unroll
    for (int t = 0; t < 4; ++t) {
        #pragma unroll
        for (int mh = 0; mh < 2; ++mh) {  // mh 0: pixel gid (c0,c1), 1: gid+8 (c2,c3)
            float s = fmaxf(acc[t][0][2 * mh]     + b1a, 0.f) * w2a
                    + fmaxf(acc[t][0][2 * mh + 1] + b1b, 0.f) * w2b
                    + fmaxf(acc[t][1][2 * mh]     + b1c, 0.f) * w2c
                    + fmaxf(acc[t][1][2 * mh + 1] + b1d, 0.f) * w2d;
            s += __shfl_xor_sync(0xffffffffu, s, 1);
            s += __shfl_xor_sync(0xffffffffu, s, 2);
            if (tig == 0) {
                const int px = 64 * half + 16 * t + gid + 8 * mh;
                const float y = 1.0f / (1.0f + __expf(-(s + b2v)));
                out[(((size_t)bb * NBLK + blk) * HH + h) * WW + px] = y;
                size_t gi = (((size_t)bb * HP + h + 4) * HP + px + 4) * CH_PAD + blk + 1;
                g_f[gi] = __float2half(y);
            }
        }
    }
}

extern "C" void kernel_launch(void* const* d_in, const int* in_sizes, int n_in,
                              void* d_out, int out_size) {
    const float* x  = (const float*)d_in[0];
    const float* w1 = (const float*)d_in[1];
    const float* b1 = (const float*)d_in[2];
    const float* w2 = (const float*)d_in[3];
    const float* b2 = (const float*)d_in[4];
    float* out = (float*)d_out;

    cudaFuncSetAttribute(dense_block_mma,
                         cudaFuncAttributeMaxDynamicSharedMemorySize, SM_TOTAL);

    prep_w_kernel<<<NBLK * MAXCK * 81, 256>>>(w1);          // 16200 blocks
    copy_x_kernel<<<(BATCH * HH * WW) / 256, 256>>>(x);

    dim3 grid(HH / G, BATCH);                               // 16 x 16 = 256 CTAs
    for (int i = 0; i < NBLK; ++i)
        dense_block_mma<<<grid, NT, SM_TOTAL>>>(b1, w2, b2, out, i);
}

// round 15
// speedup vs baseline: 3.0928x; 1.1924x over previous
#include <cuda_runtime.h>
#include <cuda_fp16.h>
#include <stdint.h>

#define BATCH 16
#define HH    128
#define WW    128
#define HID   16
#define KS    9
#define NBLK  50
#define CH_PAD 64
#define HP    136            // 128 + 4 halo each side
#define G     8              // output rows per CTA (2 warps per row)
#define MAXCK 4
#define NT    512            // threads per CTA (16 warps)

#define SM_A_BYTES (16 * HP * 32)        // 16 rows x 136 slots x 32B = 69632 (single plane)
#define SM_B_BYTES (81 * 512)            // 81 taps x [c16][oc16] fp16 = 41472
#define SM_TOTAL   (SM_A_BYTES + SM_B_BYTES)   // 111104  -> 2 CTAs/SM

// features, single fp16 plane, channel-interleaved: ((b*HP+h)*HP+x)*CH_PAD + c ; halo 0
__device__ __align__(16) __half g_f[(size_t)BATCH * HP * HP * CH_PAD];
// weights per (blk,ck): [tap81][c16][oc16] fp16, 256 elems/tap
__device__ __align__(16) __half g_wb[(size_t)NBLK * MAXCK * 81 * 256];

__device__ __forceinline__ uint32_t sptr(const void* p) {
    return (uint32_t)__cvta_generic_to_shared(p);
}
__device__ __forceinline__ void ldsm4(uint32_t* r, uint32_t a) {
    asm volatile("ldmatrix.sync.aligned.m8n8.x4.shared.b16 {%0,%1,%2,%3}, [%4];"
        : "=r"(r[0]), "=r"(r[1]), "=r"(r[2]), "=r"(r[3]) : "r"(a));
}
__device__ __forceinline__ void ldsm4t(uint32_t* r, uint32_t a) {
    asm volatile("ldmatrix.sync.aligned.m8n8.x4.trans.shared.b16 {%0,%1,%2,%3}, [%4];"
        : "=r"(r[0]), "=r"(r[1]), "=r"(r[2]), "=r"(r[3]) : "r"(a));
}
__device__ __forceinline__ void mma16816(float* c, const uint32_t* a,
                                         uint32_t b0, uint32_t b1) {
    asm volatile(
        "mma.sync.aligned.m16n8k16.row.col.f32.f16.f16.f32 "
        "{%0,%1,%2,%3},{%4,%5,%6,%7},{%8,%9},{%0,%1,%2,%3};"
        : "+f"(c[0]), "+f"(c[1]), "+f"(c[2]), "+f"(c[3])
        : "r"(a[0]), "r"(a[1]), "r"(a[2]), "r"(a[3]), "r"(b0), "r"(b1));
}

// ---- prep: fp16 weights, layout [tap][c16][oc16] ----
__global__ void prep_w_kernel(const float* __restrict__ w1) {
    int bi  = blockIdx.x;                 // NBLK*MAXCK*81
    int tap = bi % 81;
    int ck  = (bi / 81) & 3;
    int blk = bi / (81 * 4);
    int oc  = threadIdx.x & 15;
    int c   = threadIdx.x >> 4;
    int cg  = ck * 16 + c;
    float w = 0.f;
    if (cg < blk + 1)
        w = w1[(((size_t)blk * HID + oc) * (NBLK + 1) + cg) * 81 + tap];
    size_t base = ((size_t)(blk * MAXCK + ck) * 81 + tap) * 256;
    g_wb[base + c * 16 + oc] = __float2half(w);
}

__global__ void copy_x_kernel(const float* __restrict__ x) {
    int t = blockIdx.x * blockDim.x + threadIdx.x;   // b*H*W
    int w = t & (WW - 1), h = (t >> 7) & (HH - 1), b = t >> 14;
    size_t gi = (((size_t)b * HP + h + 4) * HP + w + 4) * CH_PAD;
    g_f[gi] = __float2half(x[t]);
}

__global__ void __launch_bounds__(NT, 2) dense_block_mma(
    const float* __restrict__ b1, const float* __restrict__ w2,
    const float* __restrict__ b2, float* __restrict__ out, int blk)
{
    extern __shared__ __align__(128) char smem[];
    const int tid  = threadIdx.x;
    const int wid  = tid >> 5;           // 0..15
    const int lane = tid & 31;
    const int row  = wid >> 1;           // output row within CTA (0..7)
    const int half = wid & 1;            // pixel half: 0 -> px 0-63, 1 -> 64-127
    const int gid  = lane >> 2;          // 0..7
    const int tig  = lane & 3;           // 0..3
    const int r0   = blockIdx.x * G;     // output row base
    const int bb   = blockIdx.y;

    const uint32_t sA = sptr(smem);
    const uint32_t sB = sA + SM_A_BYTES;
    const uint32_t laneoff = (uint32_t)((lane & 15) * 32 + (lane >> 4) * 16);
    // B tap is 512B: 16 rows x 32B; ldsm4t needs rows 0..15 + col-half
    const uint32_t laneoffB = (uint32_t)((lane & 15) * 32 + (lane >> 4) * 16);

    float acc[4][2][4];   // 4 m-tiles x 2 oc-halves x 4
    #pragma unroll
    for (int t = 0; t < 4; ++t)
        #pragma unroll
        for (int nh = 0; nh < 2; ++nh)
            #pragma unroll
            for (int q = 0; q < 4; ++q) acc[t][nh][q] = 0.f;

    const int nchunks = (blk + 16) >> 4;

    for (int ck = 0; ck < nchunks; ++ck) {
        __syncthreads();   // previous chunk's readers done

        // B: straight 41472B copy
        {
            const float4* src = (const float4*)(g_wb + ((size_t)blk * MAXCK + ck) * 81 * 256);
            float4* dst = (float4*)(smem + SM_A_BYTES);
            for (int i = tid; i < SM_B_BYTES / 16; i += NT) dst[i] = src[i];
        }
        // A: 16 rows x 136 slots, single fp16 plane (32B per slot)
        {
            const int c0 = ck * 16;
            float4* pa = (float4*)smem;
            for (int s = tid; s < 16 * HP; s += NT) {
                int lr = s / HP, xs = s - lr * HP;
                size_t gi = (((size_t)bb * HP + r0 + lr) * HP + xs) * CH_PAD + c0;
                int d = s * 2;
                pa[d]     = *(const float4*)(g_f + gi);
                pa[d + 1] = *(const float4*)(g_f + gi + 8);
            }
        }
        __syncthreads();

        #pragma unroll 1
        for (int kh = 0; kh < KS; ++kh) {
            const uint32_t aRow = sA + (row + kh) * 4352 + laneoff
                                + (uint32_t)(64 * half) * 32;
            #pragma unroll 1
            for (int kw = 0; kw < KS; ++kw) {
                const uint32_t bTap = sB + (kh * KS + kw) * 512 + laneoffB;
                uint32_t bh[4];
                ldsm4t(bh, bTap);        // [c16][oc16]
                #pragma unroll
                for (int t = 0; t < 4; ++t) {
                    const uint32_t aoff = (uint32_t)((16 * t + kw) * 32);
                    uint32_t a[4];
                    ldsm4(a, aRow + aoff);
                    mma16816(acc[t][0], a, bh[0], bh[1]);
                    mma16816(acc[t][1], a, bh[2], bh[3]);
                }
            }
        }
    }

    // ---- epilogue ----
    // thread's 4 output channels: o0=2*tig, o0+1, o0+8, o0+9
    const int o0 = 2 * tig;
    const float b1a = __ldg(&b1[blk * HID + o0]);
    const float b1b = __ldg(&b1[blk * HID + o0 + 1]);
    const float b1c = __ldg(&b1[blk * HID + o0 + 8]);
    const float b1d = __ldg(&b1[blk * HID + o0 + 9]);
    const float w2a = __ldg(&w2[blk * HID + o0]);
    const float w2b = __ldg(&w2[blk * HID + o0 + 1]);
    const float w2c = __ldg(&w2[blk * HID + o0 + 8]);
    const float w2d = __ldg(&w2[blk * HID + o0 + 9]);
    const float b2v = __ldg(&b2[blk]);
    const int h = r0 + row;

    #pragma unroll
    for (int t = 0; t < 4; ++t) {
        #pragma unroll
        for (int mh = 0; mh < 2; ++mh) {  // mh 0: pixel gid (c0,c1), 1: gid+8 (c2,c3)
            float s = fmaxf(acc[t][0][2 * mh]     + b1a, 0.f) * w2a
                    + fmaxf(acc[t][0][2 * mh + 1] + b1b, 0.f) * w2b
                    + fmaxf(acc[t][1][2 * mh]     + b1c, 0.f) * w2c
                    + fmaxf(acc[t][1][2 * mh + 1] + b1d, 0.f) * w2d;
            s += __shfl_xor_sync(0xffffffffu, s, 1);
            s += __shfl_xor_sync(0xffffffffu, s, 2);
            if (tig == 0) {
                const int px = 64 * half + 16 * t + gid + 8 * mh;
                const float y = 1.0f / (1.0f + __expf(-(s + b2v)));
                out[(((size_t)bb * NBLK + blk) * HH + h) * WW + px] = y;
                size_t gi = (((size_t)bb * HP + h + 4) * HP + px + 4) * CH_PAD + blk + 1;
                g_f[gi] = __float2half(y);
            }
        }
    }
}

extern "C" void kernel_launch(void* const* d_in, const int* in_sizes, int n_in,
                              void* d_out, int out_size) {
    const float* x  = (const float*)d_in[0];
    const float* w1 = (const float*)d_in[1];
    const float* b1 = (const float*)d_in[2];
    const float* w2 = (const float*)d_in[3];
    const float* b2 = (const float*)d_in[4];
    float* out = (float*)d_out;

    cudaFuncSetAttribute(dense_block_mma,
                         cudaFuncAttributeMaxDynamicSharedMemorySize, SM_TOTAL);

    prep_w_kernel<<<NBLK * MAXCK * 81, 256>>>(w1);          // 16200 blocks
    copy_x_kernel<<<(BATCH * HH * WW) / 256, 256>>>(x);

    dim3 grid(HH / G, BATCH);                               // 16 x 16 = 256 CTAs
    for (int i = 0; i < NBLK; ++i)
        dense_block_mma<<<grid, NT, SM_TOTAL>>>(b1, w2, b2, out, i);
}

// round 16
// speedup vs baseline: 5.2948x; 1.7120x over previous
#include <cuda_runtime.h>
#include <cuda_fp16.h>
#include <stdint.h>

#define BATCH 16
#define HH    128
#define WW    128
#define HID   16
#define KS    9
#define NBLK  50
#define CH_PAD 64
#define HP    136            // 128 + 4 halo each side
#define G     8              // output rows per CTA (2 warps per row)
#define MAXCK 4
#define NT    512            // threads per CTA (16 warps)

#define SM_A_BYTES (16 * HP * 32)        // 16 rows x 136 slots x 32B = 69632 (single plane)
#define SM_B_BYTES (81 * 512)            // 81 taps x [c16][oc16] fp16 = 41472
#define SM_TOTAL   (SM_A_BYTES + SM_B_BYTES)   // 111104  -> 2 CTAs/SM

// features, single fp16 plane, channel-interleaved: ((b*HP+h)*HP+x)*CH_PAD + c ; halo 0
__device__ __align__(16) __half g_f[(size_t)BATCH * HP * HP * CH_PAD];
// weights per (blk,ck): [tap81][c16][oc16] fp16, 256 elems/tap, PRE-SWIZZLED for ldsm
__device__ __align__(16) __half g_wb[(size_t)NBLK * MAXCK * 81 * 256];

__device__ __forceinline__ uint32_t sptr(const void* p) {
    return (uint32_t)__cvta_generic_to_shared(p);
}
__device__ __forceinline__ void ldsm4(uint32_t* r, uint32_t a) {
    asm volatile("ldmatrix.sync.aligned.m8n8.x4.shared.b16 {%0,%1,%2,%3}, [%4];"
        : "=r"(r[0]), "=r"(r[1]), "=r"(r[2]), "=r"(r[3]) : "r"(a));
}
__device__ __forceinline__ void ldsm4t(uint32_t* r, uint32_t a) {
    asm volatile("ldmatrix.sync.aligned.m8n8.x4.trans.shared.b16 {%0,%1,%2,%3}, [%4];"
        : "=r"(r[0]), "=r"(r[1]), "=r"(r[2]), "=r"(r[3]) : "r"(a));
}
__device__ __forceinline__ void mma16816(float* c, const uint32_t* a,
                                         uint32_t b0, uint32_t b1) {
    asm volatile(
        "mma.sync.aligned.m16n8k16.row.col.f32.f16.f16.f32 "
        "{%0,%1,%2,%3},{%4,%5,%6,%7},{%8,%9},{%0,%1,%2,%3};"
        : "+f"(c[0]), "+f"(c[1]), "+f"(c[2]), "+f"(c[3])
        : "r"(a[0]), "r"(a[1]), "r"(a[2]), "r"(a[3]), "r"(b0), "r"(b1));
}

// ---- prep: fp16 weights, layout [tap][c16][oc16], bank-swizzled ----
// element offset within tap = ((c*16 + (oc>>3)*8) ^ ((c&4)<<1)) + (oc&7)
__global__ void prep_w_kernel(const float* __restrict__ w1) {
    int bi  = blockIdx.x;                 // NBLK*MAXCK*81
    int tap = bi % 81;
    int ck  = (bi / 81) & 3;
    int blk = bi / (81 * 4);
    int oc  = threadIdx.x & 15;
    int c   = threadIdx.x >> 4;
    int cg  = ck * 16 + c;
    float w = 0.f;
    if (cg < blk + 1)
        w = w1[(((size_t)blk * HID + oc) * (NBLK + 1) + cg) * 81 + tap];
    size_t base = ((size_t)(blk * MAXCK + ck) * 81 + tap) * 256;
    int off = ((c * 16 + (oc >> 3) * 8) ^ ((c & 4) << 1)) + (oc & 7);
    g_wb[base + off] = __float2half(w);
}

__global__ void copy_x_kernel(const float* __restrict__ x) {
    int t = blockIdx.x * blockDim.x + threadIdx.x;   // b*H*W
    int w = t & (WW - 1), h = (t >> 7) & (HH - 1), b = t >> 14;
    size_t gi = (((size_t)b * HP + h + 4) * HP + w + 4) * CH_PAD;
    g_f[gi] = __float2half(x[t]);
}

__global__ void __launch_bounds__(NT, 2) dense_block_mma(
    const float* __restrict__ b1, const float* __restrict__ w2,
    const float* __restrict__ b2, float* __restrict__ out, int blk)
{
    extern __shared__ __align__(128) char smem[];
    const int tid  = threadIdx.x;
    const int wid  = tid >> 5;           // 0..15
    const int lane = tid & 31;
    const int row  = wid >> 1;           // output row within CTA (0..7)
    const int half = wid & 1;            // pixel half: 0 -> px 0-63, 1 -> 64-127
    const int gid  = lane >> 2;          // 0..7
    const int tig  = lane & 3;           // 0..3
    const int l15  = lane & 15;
    const int r0   = blockIdx.x * G;     // output row base
    const int bb   = blockIdx.y;

    const uint32_t sA = sptr(smem);
    const uint32_t sB = sA + SM_A_BYTES;
    const uint32_t laneoff = (uint32_t)(l15 * 32 + (lane >> 4) * 16);
    // B lane offset pre-swizzled (per-thread constant, conflict-free rows)
    const uint32_t laneoffB = (uint32_t)((l15 * 32 + (lane >> 4) * 16) ^ ((l15 & 4) << 2));

    float acc[4][2][4];   // 4 m-tiles x 2 oc-halves x 4
    #pragma unroll
    for (int t = 0; t < 4; ++t)
        #pragma unroll
        for (int nh = 0; nh < 2; ++nh)
            #pragma unroll
            for (int q = 0; q < 4; ++q) acc[t][nh][q] = 0.f;

    const int nchunks = (blk + 16) >> 4;

    for (int ck = 0; ck < nchunks; ++ck) {
        __syncthreads();   // previous chunk's readers done

        // B: straight 41472B copy (already swizzled in gmem)
        {
            const float4* src = (const float4*)(g_wb + ((size_t)blk * MAXCK + ck) * 81 * 256);
            float4* dst = (float4*)(smem + SM_A_BYTES);
            for (int i = tid; i < SM_B_BYTES / 16; i += NT) dst[i] = src[i];
        }
        // A: 16 rows x 136 slots, single fp16 plane, halves swapped when xs&4
        {
            const int c0 = ck * 16;
            float4* pa = (float4*)smem;
            for (int s = tid; s < 16 * HP; s += NT) {
                int lr = s / HP, xs = s - lr * HP;
                size_t gi = (((size_t)bb * HP + r0 + lr) * HP + xs) * CH_PAD + c0;
                int d  = s * 2;
                int sw = (xs >> 2) & 1;
                pa[d + sw]       = *(const float4*)(g_f + gi);       // ch 0-7
                pa[d + 1 - sw]   = *(const float4*)(g_f + gi + 8);   // ch 8-15
            }
        }
        __syncthreads();

        #pragma unroll 1
        for (int kh = 0; kh < KS; ++kh) {
            const uint32_t aRow = sA + (row + kh) * 4352 + laneoff
                                + (uint32_t)(64 * half) * 32;
            #pragma unroll 1
            for (int kw = 0; kw < KS; ++kw) {
                const uint32_t x4   = (uint32_t)(((kw + l15) & 4) << 2);
                const uint32_t bTap = sB + (kh * KS + kw) * 512 + laneoffB;
                uint32_t bh[4];
                ldsm4t(bh, bTap);        // [c16][oc16]
                #pragma unroll
                for (int t = 0; t < 4; ++t) {
                    const uint32_t aoff = (uint32_t)((16 * t + kw) * 32);
                    uint32_t a[4];
                    ldsm4(a, (aRow + aoff) ^ x4);
                    mma16816(acc[t][0], a, bh[0], bh[1]);
                    mma16816(acc[t][1], a, bh[2], bh[3]);
                }
            }
        }
    }

    // ---- epilogue ----
    // thread's 4 output channels: o0=2*tig, o0+1, o0+8, o0+9
    const int o0 = 2 * tig;
    const float b1a = __ldg(&b1[blk * HID + o0]);
    const float b1b = __ldg(&b1[blk * HID + o0 + 1]);
    const float b1c = __ldg(&b1[blk * HID + o0 + 8]);
    const float b1d = __ldg(&b1[blk * HID + o0 + 9]);
    const float w2a = __ldg(&w2[blk * HID + o0]);
    const float w2b = __ldg(&w2[blk * HID + o0 + 1]);
    const float w2c = __ldg(&w2[blk * HID + o0 + 8]);
    const float w2d = __ldg(&w2[blk * HID + o0 + 9]);
    const float b2v = __ldg(&b2[blk]);
    const int h = r0 + row;

    #pragma unroll
    for (int t = 0; t < 4; ++t) {
        #pragma unroll
        for (int mh = 0; mh < 2; ++mh) {  // mh 0: pixel gid (c0,c1), 1: gid+8 (c2,c3)
            float s = fmaxf(acc[t][0][2 * mh]     + b1a, 0.f) * w2a
                    + fmaxf(acc[t][0][2 * mh + 1] + b1b, 0.f) * w2b
                    + fmaxf(acc[t][1][2 * mh]     + b1c, 0.f) * w2c
                    + fmaxf(acc[t][1][2 * mh + 1] + b1d, 0.f) * w2d;
            s += __shfl_xor_sync(0xffffffffu, s, 1);
            s += __shfl_xor_sync(0xffffffffu, s, 2);
            if (tig == 0) {
                const int px = 64 * half + 16 * t + gid + 8 * mh;
                const float y = 1.0f / (1.0f + __expf(-(s + b2v)));
                out[(((size_t)bb * NBLK + blk) * HH + h) * WW + px] = y;
                size_t gi = (((size_t)bb * HP + h + 4) * HP + px + 4) * CH_PAD + blk + 1;
                g_f[gi] = __float2half(y);
            }
        }
    }
}

extern "C" void kernel_launch(void* const* d_in, const int* in_sizes, int n_in,
                              void* d_out, int out_size) {
    const float* x  = (const float*)d_in[0];
    const float* w1 = (const float*)d_in[1];
    const float* b1 = (const float*)d_in[2];
    const float* w2 = (const float*)d_in[3];
    const float* b2 = (const float*)d_in[4];
    float* out = (float*)d_out;

    cudaFuncSetAttribute(dense_block_mma,
                         cudaFuncAttributeMaxDynamicSharedMemorySize, SM_TOTAL);

    prep_w_kernel<<<NBLK * MAXCK * 81, 256>>>(w1);          // 16200 blocks
    copy_x_kernel<<<(BATCH * HH * WW) / 256, 256>>>(x);

    dim3 grid(HH / G, BATCH);                               // 16 x 16 = 256 CTAs
    for (int i = 0; i < NBLK; ++i)
        dense_block_mma<<<grid, NT, SM_TOTAL>>>(b1, w2, b2, out, i);
}

// round 17
// speedup vs baseline: 5.5416x; 1.0466x over previous
#include <cuda_runtime.h>
#include <cuda_fp16.h>
#include <stdint.h>

#define BATCH 16
#define HH    128
#define WW    128
#define HID   16
#define KS    9
#define NBLK  50
#define CH_PAD 64
#define HP    136            // 128 + 4 halo each side
#define G     8              // output rows per CTA (2 warps per row)
#define MAXCK 4
#define NT    512            // threads per CTA (16 warps)

#define SM_A_BYTES (16 * HP * 32)        // 69632
#define SM_B_BYTES (81 * 512)            // 41472
#define SM_TOTAL   (SM_A_BYTES + SM_B_BYTES)   // 111104 -> 2 CTAs/SM

// features, single fp16 plane, channel-interleaved: ((b*HP+h)*HP+x)*CH_PAD + c ; halo 0
__device__ __align__(16) __half g_f[(size_t)BATCH * HP * HP * CH_PAD];
// weights per (blk,ck): [tap81][c16][oc16] fp16, 256 elems/tap, PRE-SWIZZLED for ldsm
__device__ __align__(16) __half g_wb[(size_t)NBLK * MAXCK * 81 * 256];
// inter-block arrival counters: [blk][batch], reset every kernel_launch
__device__ int g_bar[NBLK * BATCH];

__device__ __forceinline__ uint32_t sptr(const void* p) {
    return (uint32_t)__cvta_generic_to_shared(p);
}
__device__ __forceinline__ void ldsm4(uint32_t* r, uint32_t a) {
    asm volatile("ldmatrix.sync.aligned.m8n8.x4.shared.b16 {%0,%1,%2,%3}, [%4];"
        : "=r"(r[0]), "=r"(r[1]), "=r"(r[2]), "=r"(r[3]) : "r"(a));
}
__device__ __forceinline__ void ldsm4t(uint32_t* r, uint32_t a) {
    asm volatile("ldmatrix.sync.aligned.m8n8.x4.trans.shared.b16 {%0,%1,%2,%3}, [%4];"
        : "=r"(r[0]), "=r"(r[1]), "=r"(r[2]), "=r"(r[3]) : "r"(a));
}
__device__ __forceinline__ void mma16816(float* c, const uint32_t* a,
                                         uint32_t b0, uint32_t b1) {
    asm volatile(
        "mma.sync.aligned.m16n8k16.row.col.f32.f16.f16.f32 "
        "{%0,%1,%2,%3},{%4,%5,%6,%7},{%8,%9},{%0,%1,%2,%3};"
        : "+f"(c[0]), "+f"(c[1]), "+f"(c[2]), "+f"(c[3])
        : "r"(a[0]), "r"(a[1]), "r"(a[2]), "r"(a[3]), "r"(b0), "r"(b1));
}

// ---- prep: fp16 weights, layout [tap][c16][oc16], bank-swizzled ----
__global__ void prep_w_kernel(const float* __restrict__ w1) {
    int bi  = blockIdx.x;                 // NBLK*MAXCK*81
    int tap = bi % 81;
    int ck  = (bi / 81) & 3;
    int blk = bi / (81 * 4);
    int oc  = threadIdx.x & 15;
    int c   = threadIdx.x >> 4;
    int cg  = ck * 16 + c;
    float w = 0.f;
    if (cg < blk + 1)
        w = w1[(((size_t)blk * HID + oc) * (NBLK + 1) + cg) * 81 + tap];
    size_t base = ((size_t)(blk * MAXCK + ck) * 81 + tap) * 256;
    int off = ((c * 16 + (oc >> 3) * 8) ^ ((c & 4) << 1)) + (oc & 7);
    g_wb[base + off] = __float2half(w);
}

__global__ void copy_x_kernel(const float* __restrict__ x) {
    int t = blockIdx.x * blockDim.x + threadIdx.x;   // b*H*W
    int w = t & (WW - 1), h = (t >> 7) & (HH - 1), b = t >> 14;
    size_t gi = (((size_t)b * HP + h + 4) * HP + w + 4) * CH_PAD;
    g_f[gi] = __float2half(x[t]);
}

__global__ void reset_bar_kernel() {
    int i = blockIdx.x * blockDim.x + threadIdx.x;
    if (i < NBLK * BATCH) g_bar[i] = 0;
}

__global__ void __launch_bounds__(NT, 2) dense_all_mma(
    const float* __restrict__ b1, const float* __restrict__ w2,
    const float* __restrict__ b2, float* __restrict__ out)
{
    extern __shared__ __align__(128) char smem[];
    const int tid  = threadIdx.x;
    const int wid  = tid >> 5;           // 0..15
    const int lane = tid & 31;
    const int row  = wid >> 1;           // output row within CTA (0..7)
    const int half = wid & 1;            // pixel half
    const int gid  = lane >> 2;          // 0..7
    const int tig  = lane & 3;           // 0..3
    const int l15  = lane & 15;
    const int r0   = blockIdx.x * G;     // output row base
    const int bb   = blockIdx.y;

    const uint32_t sA = sptr(smem);
    const uint32_t sB = sA + SM_A_BYTES;
    const uint32_t laneoff  = (uint32_t)(l15 * 32 + (lane >> 4) * 16);
    const uint32_t laneoffB = (uint32_t)((l15 * 32 + (lane >> 4) * 16) ^ ((l15 & 4) << 2));

    for (int blk = 0; blk < NBLK; ++blk) {
        const int nchunks = (blk + 16) >> 4;

        float acc[4][2][4];
        #pragma unroll
        for (int t = 0; t < 4; ++t)
            #pragma unroll
            for (int nh = 0; nh < 2; ++nh)
                #pragma unroll
                for (int q = 0; q < 4; ++q) acc[t][nh][q] = 0.f;

        for (int ck = 0; ck < nchunks; ++ck) {
            // before the chunk containing channel `blk`, wait for block blk-1
            // of this batch image (16 CTAs) to finish its epilogue stores.
            if (ck == nchunks - 1 && blk > 0) {
                if (tid == 0) {
                    volatile int* flag = &g_bar[(blk - 1) * BATCH + bb];
                    for (int i = 0; i < (1 << 22); ++i)
                        if (*flag == BATCH) break;
                }
                __syncthreads();
            }
            __syncthreads();   // previous chunk's smem readers done

            // B: 41472B copy (already swizzled in gmem)
            {
                const float4* src = (const float4*)(g_wb + ((size_t)blk * MAXCK + ck) * 81 * 256);
                float4* dst = (float4*)(smem + SM_A_BYTES);
                for (int i = tid; i < SM_B_BYTES / 16; i += NT) dst[i] = src[i];
            }
            // A: 16 rows x 136 slots, halves swapped when xs&4
            {
                const int c0 = ck * 16;
                float4* pa = (float4*)smem;
                for (int s = tid; s < 16 * HP; s += NT) {
                    int lr = s / HP, xs = s - lr * HP;
                    size_t gi = (((size_t)bb * HP + r0 + lr) * HP + xs) * CH_PAD + c0;
                    int d  = s * 2;
                    int sw = (xs >> 2) & 1;
                    pa[d + sw]     = *(const float4*)(g_f + gi);       // ch 0-7
                    pa[d + 1 - sw] = *(const float4*)(g_f + gi + 8);   // ch 8-15
                }
            }
            __syncthreads();

            #pragma unroll 1
            for (int kh = 0; kh < KS; ++kh) {
                const uint32_t aRow = sA + (row + kh) * 4352 + laneoff
                                    + (uint32_t)(64 * half) * 32;
                #pragma unroll 1
                for (int kw = 0; kw < KS; ++kw) {
                    const uint32_t x4   = (uint32_t)(((kw + l15) & 4) << 2);
                    const uint32_t bTap = sB + (kh * KS + kw) * 512 + laneoffB;
                    uint32_t bh[4];
                    ldsm4t(bh, bTap);
                    #pragma unroll
                    for (int t = 0; t < 4; ++t) {
                        const uint32_t aoff = (uint32_t)((16 * t + kw) * 32);
                        uint32_t a[4];
                        ldsm4(a, (aRow + aoff) ^ x4);
                        mma16816(acc[t][0], a, bh[0], bh[1]);
                        mma16816(acc[t][1], a, bh[2], bh[3]);
                    }
                }
            }
        }

        // ---- epilogue ----
        const int o0 = 2 * tig;
        const float b1a = __ldg(&b1[blk * HID + o0]);
        const float b1b = __ldg(&b1[blk * HID + o0 + 1]);
        const float b1c = __ldg(&b1[blk * HID + o0 + 8]);
        const float b1d = __ldg(&b1[blk * HID + o0 + 9]);
        const float w2a = __ldg(&w2[blk * HID + o0]);
        const float w2b = __ldg(&w2[blk * HID + o0 + 1]);
        const float w2c = __ldg(&w2[blk * HID + o0 + 8]);
        const float w2d = __ldg(&w2[blk * HID + o0 + 9]);
        const float b2v = __ldg(&b2[blk]);
        const int h = r0 + row;

        #pragma unroll
        for (int t = 0; t < 4; ++t) {
            #pragma unroll
            for (int mh = 0; mh < 2; ++mh) {
                float s = fmaxf(acc[t][0][2 * mh]     + b1a, 0.f) * w2a
                        + fmaxf(acc[t][0][2 * mh + 1] + b1b, 0.f) * w2b
                        + fmaxf(acc[t][1][2 * mh]     + b1c, 0.f) * w2c
                        + fmaxf(acc[t][1][2 * mh + 1] + b1d, 0.f) * w2d;
                s += __shfl_xor_sync(0xffffffffu, s, 1);
                s += __shfl_xor_sync(0xffffffffu, s, 2);
                if (tig == 0) {
                    const int px = 64 * half + 16 * t + gid + 8 * mh;
                    const float y = 1.0f / (1.0f + __expf(-(s + b2v)));
                    out[(((size_t)bb * NBLK + blk) * HH + h) * WW + px] = y;
                    size_t gi = (((size_t)bb * HP + h + 4) * HP + px + 4) * CH_PAD + blk + 1;
                    g_f[gi] = __float2half(y);
                }
            }
        }

        // ---- signal: stores visible device-wide, then arrive ----
        __threadfence();
        __syncthreads();
        if (tid == 0 && blk < NBLK - 1)
            atomicAdd(&g_bar[blk * BATCH + bb], 1);
    }
}

extern "C" void kernel_launch(void* const* d_in, const int* in_sizes, int n_in,
                              void* d_out, int out_size) {
    const float* x  = (const float*)d_in[0];
    const float* w1 = (const float*)d_in[1];
    const float* b1 = (const float*)d_in[2];
    const float* w2 = (const float*)d_in[3];
    const float* b2 = (const float*)d_in[4];
    float* out = (float*)d_out;

    cudaFuncSetAttribute(dense_all_mma,
                         cudaFuncAttributeMaxDynamicSharedMemorySize, SM_TOTAL);

    prep_w_kernel<<<NBLK * MAXCK * 81, 256>>>(w1);          // 16200 blocks
    copy_x_kernel<<<(BATCH * HH * WW) / 256, 256>>>(x);
    reset_bar_kernel<<<(NBLK * BATCH + 255) / 256, 256>>>();

    dim3 grid(HH / G, BATCH);                               // 16 x 16 = 256 CTAs
    dense_all_mma<<<grid, NT, SM_TOTAL>>>(b1, w2, b2, out);
}